// round 15
// baseline (speedup 1.0000x reference)
#include <cuda_runtime.h>
#include <cstdint>
#include <cstddef>

#define NMAX 100000
#define EMAX 800000
#define HIDD 96
#define SCAN_BLK 1024

// ---------------- scratch (no allocations allowed) ----------------
__device__ __align__(16) float g_dinv[NMAX];
__device__ __align__(16) float g_hA[(size_t)NMAX * HIDD];   // GEMM out, prescaled by dinv[row]
__device__ __align__(16) float g_agg[(size_t)NMAX * HIDD];  // gather output (pre-BN)
__device__ __align__(16) float g_stats[2 * 192];            // per-layer [sum(96) | sumsq(96)]
__device__ int g_cnt[NMAX];
__device__ int g_off[NMAX + 1];
__device__ int g_cur[NMAX];
__device__ int g_srcs[EMAX];
__device__ int g_pub[128];                                  // decoupled-scan publish slots

// ---------------- packed fp32x2 FMA (sm_103a FFMA2) ----------------
__device__ __forceinline__ float2 ffma2(float2 a, float2 b, float2 c) {
    unsigned long long ua = *reinterpret_cast<unsigned long long*>(&a);
    unsigned long long ub = *reinterpret_cast<unsigned long long*>(&b);
    unsigned long long uc = *reinterpret_cast<unsigned long long*>(&c);
    unsigned long long ud;
    asm("fma.rn.f32x2 %0, %1, %2, %3;" : "=l"(ud) : "l"(ua), "l"(ub), "l"(uc));
    return *reinterpret_cast<float2*>(&ud);
}

// ---------------- zero everything that needs zeroing (one kernel) ----------------
__global__ void k_zero(int N, int nb) {
    int i = blockIdx.x * blockDim.x + threadIdx.x;
    if (i < N) { g_cnt[i] = 0; g_cur[i] = 0; }
    if (i < nb) g_pub[i] = 0;
    if (i < 2 * 192) g_stats[i] = 0.f;
}
__global__ void k_hist(const int* __restrict__ dst, int E) {
    int e = blockIdx.x * blockDim.x + threadIdx.x;
    if (e < E) atomicAdd(&g_cnt[dst[e]], 1);
}

// ---------------- fused exclusive scan + dinv (decoupled raking) ----------------
__global__ __launch_bounds__(SCAN_BLK)
void k_scan(int N) {
    __shared__ int s[SCAN_BLK];
    __shared__ int wsum[32];
    __shared__ int base_sh;
    const int tid = threadIdx.x;
    const int b = blockIdx.x;
    const int i = b * SCAN_BLK + tid;
    const int myc = (i < N) ? g_cnt[i] : 0;

    s[tid] = myc;
    __syncthreads();
#pragma unroll
    for (int o = 1; o < SCAN_BLK; o <<= 1) {
        int t = (tid >= o) ? s[tid - o] : 0;
        __syncthreads();
        s[tid] += t;
        __syncthreads();
    }

    if (tid == SCAN_BLK - 1) atomicExch(&g_pub[b], s[SCAN_BLK - 1] + 1);

    int p = 0;
    if (tid < b) {
        int v;
        do { v = atomicAdd(&g_pub[tid], 0); } while (v == 0);
        p = v - 1;
    }
#pragma unroll
    for (int o = 16; o > 0; o >>= 1) p += __shfl_xor_sync(0xFFFFFFFFu, p, o);
    if ((tid & 31) == 0) wsum[tid >> 5] = p;
    __syncthreads();
    if (tid == 0) {
        int a = 0;
#pragma unroll
        for (int wgi = 0; wgi < 32; wgi++) a += wsum[wgi];
        base_sh = a;
    }
    __syncthreads();
    const int base = base_sh;

    if (i < N) {
        g_off[i + 1] = base + s[tid];
        g_dinv[i] = rsqrtf((float)(myc + 1));   // +1 self loop
    }
    if (b == 0 && tid == 0) g_off[0] = 0;
}

__global__ void k_reorder(const int* __restrict__ src, const int* __restrict__ dst, int E) {
    int e = blockIdx.x * blockDim.x + threadIdx.x;
    if (e < E) {
        int d = dst[e];
        int pos = g_off[d] + atomicAdd(&g_cur[d], 1);
        g_srcs[pos] = src[e];
    }
}

// ---------------- GEMM: g_hA[N,OUT] = dinv[row] * (act(X)[N,K] @ W[K,OUT]) ----------------
// R10 structure (direct X LDG, full W in SMEM, no inner barriers) with an
// FFMA2 (f32x2) core: accumulators are column-pair float2s; per (kk,row) one
// {x,x} pack feeds 4 packed FMAs. MODE 0: X=ptr, no act. MODE 1/2: X=g_agg
// with fused BN(stats MODE-1)+ReLU applied at the X load.
__device__ __forceinline__ float f4c(const float4& v, int kk) {
    switch (kk) { case 0: return v.x; case 1: return v.y; case 2: return v.z; default: return v.w; }
}

template <int K, int OUT, int RY, int MODE>
__global__ __launch_bounds__((OUT / 8) * RY)
void gemm_kernel(const float* __restrict__ Xarg, const float* __restrict__ W,
                 const float* __restrict__ gamma, const float* __restrict__ beta, int N) {
    constexpr int CG = OUT / 8;        // thread col-groups (8 cols each)
    constexpr int C4 = OUT / 4;        // float4s per W row
    constexpr int NT = CG * RY;        // threads
    constexpr int SAB = (MODE != 0) ? K : 1;

    __shared__ float4 Ws[K * C4];      // full W
    __shared__ float sa[SAB];
    __shared__ float sc[SAB];

    const int tid = threadIdx.y * CG + threadIdx.x;
    const float4* W4 = (const float4*)W;
    for (int i = tid; i < K * C4; i += NT) Ws[i] = W4[i];
    if (MODE) {
        const float* st = g_stats + (MODE - 1) * 192;
        for (int f = tid; f < K; f += NT) {
            float invN = 1.0f / (float)N;
            float mu = st[f] * invN;
            float var = st[96 + f] * invN - mu * mu;
            float a = gamma[f] * rsqrtf(var + 1e-5f);
            sa[f] = a;
            sc[f] = beta[f] - mu * a;
        }
    }
    __syncthreads();

    const float* X = MODE ? (const float*)g_agg : Xarg;
    const int c = threadIdx.x;
    const int r0 = (blockIdx.x * RY + threadIdx.y) * 8;
    if (r0 >= N) return;
    const bool full = (r0 + 7 < N);

    const float4* X4 = (const float4*)X;
    constexpr int ldx = K / 4;

    float2 acc[8][4];
#pragma unroll
    for (int r = 0; r < 8; r++)
#pragma unroll
        for (int q = 0; q < 4; q++) acc[r][q] = make_float2(0.f, 0.f);

    for (int k4 = 0; k4 < K / 4; k4++) {
        float4 xr[8];
        float4 ba, bc;
        if (MODE) { ba = ((const float4*)sa)[k4]; bc = ((const float4*)sc)[k4]; }
#pragma unroll
        for (int r = 0; r < 8; r++) {
            int row = r0 + r;
            float4 v = (full || row < N) ? X4[(size_t)row * ldx + k4]
                                         : make_float4(0.f, 0.f, 0.f, 0.f);
            if (MODE) {
                v.x = fmaxf(ba.x * v.x + bc.x, 0.f);
                v.y = fmaxf(ba.y * v.y + bc.y, 0.f);
                v.z = fmaxf(ba.z * v.z + bc.z, 0.f);
                v.w = fmaxf(ba.w * v.w + bc.w, 0.f);
            }
            xr[r] = v;
        }
#pragma unroll
        for (int kk = 0; kk < 4; kk++) {
            float4 w0 = Ws[(k4 * 4 + kk) * C4 + 2 * c];
            float4 w1 = Ws[(k4 * 4 + kk) * C4 + 2 * c + 1];
            float2 w0a = make_float2(w0.x, w0.y), w0b = make_float2(w0.z, w0.w);
            float2 w1a = make_float2(w1.x, w1.y), w1b = make_float2(w1.z, w1.w);
#pragma unroll
            for (int r = 0; r < 8; r++) {
                float xv = f4c(xr[r], kk);
                float2 xp = make_float2(xv, xv);
                acc[r][0] = ffma2(xp, w0a, acc[r][0]);
                acc[r][1] = ffma2(xp, w0b, acc[r][1]);
                acc[r][2] = ffma2(xp, w1a, acc[r][2]);
                acc[r][3] = ffma2(xp, w1b, acc[r][3]);
            }
        }
    }

    float4* Y4 = (float4*)g_hA;
#pragma unroll
    for (int r = 0; r < 8; r++) {
        int row = r0 + r;
        if (full || row < N) {
            float dr = g_dinv[row];
            float4 a0 = make_float4(acc[r][0].x * dr, acc[r][0].y * dr,
                                    acc[r][1].x * dr, acc[r][1].y * dr);
            float4 a1 = make_float4(acc[r][2].x * dr, acc[r][2].y * dr,
                                    acc[r][3].x * dr, acc[r][3].y * dr);
            Y4[(size_t)row * C4 + 2 * c]     = a0;
            Y4[(size_t)row * C4 + 2 * c + 1] = a1;
        }
    }
}

// ---------------- gather96: warp per node, CSR in-edges ----------------
__global__ __launch_bounds__(256)
void gather96_kernel(const float* __restrict__ bias, int layer, int N) {
    __shared__ float sred[192];
    const int tid = threadIdx.x;
    for (int i = tid; i < 192; i += 256) sred[i] = 0.f;
    __syncthreads();

    const int lane = tid & 31;
    const int w = tid >> 5;
    const int c0 = lane, c1 = lane + 32, c2 = lane + 64;
    const float b0 = bias[c0], b1 = bias[c1], b2 = bias[c2];
    const int nwarps = gridDim.x * 8;

    float s0 = 0.f, s1 = 0.f, s2 = 0.f;
    float q0 = 0.f, q1 = 0.f, q2 = 0.f;

    for (int d = blockIdx.x * 8 + w; d < N; d += nwarps) {
        const int beg = g_off[d];
        const int end = g_off[d + 1];
        float a0 = 0.f, a1 = 0.f, a2 = 0.f;
        int j = beg;
        for (; j + 3 < end; j += 4) {
            int sa = g_srcs[j], sb = g_srcs[j + 1], sc = g_srcs[j + 2], se = g_srcs[j + 3];
            const float* ha = g_hA + (size_t)sa * 96;
            const float* hb = g_hA + (size_t)sb * 96;
            const float* hc = g_hA + (size_t)sc * 96;
            const float* he = g_hA + (size_t)se * 96;
            float x0a = ha[c0], x1a = ha[c1], x2a = ha[c2];
            float x0b = hb[c0], x1b = hb[c1], x2b = hb[c2];
            float x0c = hc[c0], x1c = hc[c1], x2c = hc[c2];
            float x0e = he[c0], x1e = he[c1], x2e = he[c2];
            a0 += (x0a + x0b) + (x0c + x0e);
            a1 += (x1a + x1b) + (x1c + x1e);
            a2 += (x2a + x2b) + (x2c + x2e);
        }
        for (; j < end; j++) {
            int sa = g_srcs[j];
            const float* ha = g_hA + (size_t)sa * 96;
            a0 += ha[c0]; a1 += ha[c1]; a2 += ha[c2];
        }
        const float dd = g_dinv[d];
        const float* hd = g_hA + (size_t)d * 96;
        a0 += hd[c0]; a1 += hd[c1]; a2 += hd[c2];
        float v0 = dd * a0 + b0;
        float v1 = dd * a1 + b1;
        float v2 = dd * a2 + b2;
        float* od = g_agg + (size_t)d * 96;
        od[c0] = v0; od[c1] = v1; od[c2] = v2;
        s0 += v0; s1 += v1; s2 += v2;
        q0 += v0 * v0; q1 += v1 * v1; q2 += v2 * v2;
    }

    atomicAdd(&sred[c0], s0); atomicAdd(&sred[c1], s1); atomicAdd(&sred[c2], s2);
    atomicAdd(&sred[96 + c0], q0); atomicAdd(&sred[96 + c1], q1); atomicAdd(&sred[96 + c2], q2);
    __syncthreads();
    float* st = g_stats + layer * 192;
    for (int i = tid; i < 192; i += 256) atomicAdd(&st[i], sred[i]);
}

// ---------------- layer-3: gather(32) + log_softmax, warp per node ----------------
__global__ __launch_bounds__(256)
void gather32_softmax_kernel(const float* __restrict__ b3, float* __restrict__ out, int N) {
    int d = blockIdx.x * 8 + (threadIdx.x >> 5);
    int lane = threadIdx.x & 31;
    if (d >= N) return;
    const int beg = g_off[d];
    const int end = g_off[d + 1];
    float a = 0.f;
    int j = beg;
    for (; j + 3 < end; j += 4) {
        int sa = g_srcs[j], sb = g_srcs[j + 1], sc = g_srcs[j + 2], se = g_srcs[j + 3];
        float xa = g_hA[(size_t)sa * 32 + lane];
        float xb = g_hA[(size_t)sb * 32 + lane];
        float xc = g_hA[(size_t)sc * 32 + lane];
        float xe = g_hA[(size_t)se * 32 + lane];
        a += (xa + xb) + (xc + xe);
    }
    for (; j < end; j++) {
        int sa = g_srcs[j];
        a += g_hA[(size_t)sa * 32 + lane];
    }
    float dd = g_dinv[d];
    a += g_hA[(size_t)d * 32 + lane];
    float v = dd * a + b3[lane];
    float m = v;
#pragma unroll
    for (int o = 16; o > 0; o >>= 1) m = fmaxf(m, __shfl_xor_sync(0xFFFFFFFFu, m, o));
    float s = expf(v - m);
#pragma unroll
    for (int o = 16; o > 0; o >>= 1) s += __shfl_xor_sync(0xFFFFFFFFu, s, o);
    out[(size_t)d * 32 + lane] = v - m - logf(s);
}

// ---------------- host ----------------
extern "C" void kernel_launch(void* const* d_in, const int* in_sizes, int n_in,
                              void* d_out, int out_size) {
    const float* x  = (const float*)d_in[0];
    const int* ei   = (const int*)d_in[1];   // int32 in practice (JAX x64 disabled)
    const float* W1 = (const float*)d_in[2];
    const float* b1 = (const float*)d_in[3];
    const float* W2 = (const float*)d_in[4];
    const float* b2 = (const float*)d_in[5];
    const float* W3 = (const float*)d_in[6];
    const float* b3 = (const float*)d_in[7];
    const float* g1 = (const float*)d_in[8];
    const float* be1 = (const float*)d_in[9];
    const float* g2 = (const float*)d_in[10];
    const float* be2 = (const float*)d_in[11];
    float* out = (float*)d_out;

    int N = in_sizes[0] / 128;
    int E = in_sizes[1] / 2;
    const int* src = ei;
    const int* dst = ei + E;
    int nb = (N + SCAN_BLK - 1) / SCAN_BLK;

    // --- CSR build ---
    k_zero<<<(N + 1023) / 1024, 1024>>>(N, nb);
    k_hist<<<(E + 255) / 256, 256>>>(dst, E);
    k_scan<<<nb, SCAN_BLK>>>(N);
    gemm_kernel<128, 96, 16, 0><<<(N + 127) / 128, dim3(12, 16)>>>(x, W1, nullptr, nullptr, N);
    k_reorder<<<(E + 255) / 256, 256>>>(src, dst, E);

    // --- layer 1 ---
    gather96_kernel<<<592, 256>>>(b1, 0, N);

    // --- layer 2 (BN+ReLU fused into GEMM X load) ---
    gemm_kernel<96, 96, 16, 1><<<(N + 127) / 128, dim3(12, 16)>>>(nullptr, W2, g1, be1, N);
    gather96_kernel<<<592, 256>>>(b2, 1, N);

    // --- layer 3 (BN+ReLU fused), then gather + log_softmax ---
    gemm_kernel<96, 32, 32, 2><<<(N + 255) / 256, dim3(4, 32)>>>(nullptr, W3, g2, be2, N);
    gather32_softmax_kernel<<<(N + 7) / 8, 256>>>(b3, out, N);
}

// round 16
// speedup vs baseline: 1.8112x; 1.8112x over previous
#include <cuda_runtime.h>
#include <cstdint>
#include <cstddef>

#define NMAX 100000
#define EMAX 800000
#define HIDD 96
#define SCAN_BLK 1024

// ---------------- scratch (no allocations allowed) ----------------
__device__ __align__(16) float g_dinv[NMAX];
__device__ __align__(16) float g_hA[(size_t)NMAX * HIDD];   // GEMM out, prescaled by dinv[row]
__device__ __align__(16) float g_agg[(size_t)NMAX * HIDD];  // gather output (pre-BN)
__device__ __align__(16) float g_stats[2 * 192];            // per-layer [sum(96) | sumsq(96)]
__device__ int g_cnt[NMAX];
__device__ int g_off[NMAX + 1];
__device__ int g_cur[NMAX];
__device__ int g_srcs[EMAX];
__device__ int g_pub[128];                                  // decoupled-scan publish slots

// ---------------- tf32 helpers ----------------
__device__ __forceinline__ uint32_t f2tf32(float f) {
    uint32_t r;
    asm("cvt.rna.tf32.f32 %0, %1;" : "=r"(r) : "f"(f));
    return r;
}
__device__ __forceinline__ void mma_tf32(float c[4], const uint32_t a[4],
                                         uint32_t b0, uint32_t b1) {
    asm volatile(
        "mma.sync.aligned.m16n8k8.row.col.f32.tf32.tf32.f32 "
        "{%0,%1,%2,%3},{%4,%5,%6,%7},{%8,%9},{%0,%1,%2,%3};"
        : "+f"(c[0]), "+f"(c[1]), "+f"(c[2]), "+f"(c[3])
        : "r"(a[0]), "r"(a[1]), "r"(a[2]), "r"(a[3]), "r"(b0), "r"(b1));
}

// ---------------- zero everything that needs zeroing (one kernel) ----------------
__global__ void k_zero(int N, int nb) {
    int i = blockIdx.x * blockDim.x + threadIdx.x;
    if (i < N) { g_cnt[i] = 0; g_cur[i] = 0; }
    if (i < nb) g_pub[i] = 0;
    if (i < 2 * 192) g_stats[i] = 0.f;
}
__global__ void k_hist(const int* __restrict__ dst, int E) {
    int e = blockIdx.x * blockDim.x + threadIdx.x;
    if (e < E) atomicAdd(&g_cnt[dst[e]], 1);
}

// ---------------- fused exclusive scan + dinv (decoupled raking) ----------------
__global__ __launch_bounds__(SCAN_BLK)
void k_scan(int N) {
    __shared__ int s[SCAN_BLK];
    __shared__ int wsum[32];
    __shared__ int base_sh;
    const int tid = threadIdx.x;
    const int b = blockIdx.x;
    const int i = b * SCAN_BLK + tid;
    const int myc = (i < N) ? g_cnt[i] : 0;

    s[tid] = myc;
    __syncthreads();
#pragma unroll
    for (int o = 1; o < SCAN_BLK; o <<= 1) {
        int t = (tid >= o) ? s[tid - o] : 0;
        __syncthreads();
        s[tid] += t;
        __syncthreads();
    }

    if (tid == SCAN_BLK - 1) atomicExch(&g_pub[b], s[SCAN_BLK - 1] + 1);

    int p = 0;
    if (tid < b) {
        int v;
        do { v = atomicAdd(&g_pub[tid], 0); } while (v == 0);
        p = v - 1;
    }
#pragma unroll
    for (int o = 16; o > 0; o >>= 1) p += __shfl_xor_sync(0xFFFFFFFFu, p, o);
    if ((tid & 31) == 0) wsum[tid >> 5] = p;
    __syncthreads();
    if (tid == 0) {
        int a = 0;
#pragma unroll
        for (int wgi = 0; wgi < 32; wgi++) a += wsum[wgi];
        base_sh = a;
    }
    __syncthreads();
    const int base = base_sh;

    if (i < N) {
        g_off[i + 1] = base + s[tid];
        g_dinv[i] = rsqrtf((float)(myc + 1));   // +1 self loop
    }
    if (b == 0 && tid == 0) g_off[0] = 0;
}

__global__ void k_reorder(const int* __restrict__ src, const int* __restrict__ dst, int E) {
    int e = blockIdx.x * blockDim.x + threadIdx.x;
    if (e < E) {
        int d = dst[e];
        int pos = g_off[d] + atomicAdd(&g_cur[d], 1);
        g_srcs[pos] = src[e];
    }
}

// ---------------- TF32 GEMM (OUT=96): g_hA = dinv[row] * (act(X) @ W) ----------------
// Warp computes 16 rows x 96 cols via 12x m16n8k8 tf32 MMAs per k-step.
// W staged in SMEM (tf32, stride 104 -> conflict-free B-frag LDS), K in 2 chunks.
// MODE 0: X=ptr. MODE 1: X=g_agg with BN(stats 0)+ReLU fused at the A load.
template <int K, int MODE>
__global__ __launch_bounds__(256)
void gemm_tf32_kernel(const float* __restrict__ Xarg, const float* __restrict__ W,
                      const float* __restrict__ gamma, const float* __restrict__ beta, int N) {
    constexpr int OUTC = 96;
    constexpr int WST = 104;          // SMEM stride (floats): tig*104 % 32 = tig*8 -> 32 distinct banks
    constexpr int KC = K / 2;         // K chunk (64 or 48)
    constexpr int NK = KC / 8;        // k-steps per chunk
    constexpr int SAB = (MODE != 0) ? K : 1;

    __shared__ uint32_t Ws[KC * WST];
    __shared__ float sa[SAB];
    __shared__ float sc[SAB];

    const int tid = threadIdx.x;
    const int lane = tid & 31;
    const int w = tid >> 5;
    const int g = lane >> 2;          // groupID 0..7
    const int tig = lane & 3;         // thread-in-group 0..3

    if (MODE) {
        const float* st = g_stats + (MODE - 1) * 192;
        float invN = 1.0f / (float)N;
        for (int f = tid; f < K; f += 256) {
            float mu = st[f] * invN;
            float var = st[96 + f] * invN - mu * mu;
            float a = gamma[f] * rsqrtf(var + 1e-5f);
            sa[f] = a;
            sc[f] = beta[f] - mu * a;
        }
    }

    const float* X = MODE ? (const float*)g_agg : Xarg;
    const int blockRow = blockIdx.x * 128;
    const int r0 = blockRow + w * 16;
    const int ra = r0 + g;
    const int rb = r0 + g + 8;
    const bool full = (blockRow + 128 <= N);

    float c[12][4];
#pragma unroll
    for (int nt = 0; nt < 12; nt++)
#pragma unroll
        for (int q = 0; q < 4; q++) c[nt][q] = 0.f;

    for (int ch = 0; ch < 2; ch++) {
        __syncthreads();
        // stage W chunk (rows ch*KC .. ch*KC+KC-1), convert to tf32
        for (int i = tid; i < KC * OUTC; i += 256) {
            int k = i / OUTC, n = i - (i / OUTC) * OUTC;
            Ws[k * WST + n] = f2tf32(W[(size_t)(ch * KC + k) * OUTC + n]);
        }
        __syncthreads();

        if (r0 < N) {
#pragma unroll
            for (int ks = 0; ks < NK; ks++) {
                const int k0g = ch * KC + ks * 8;   // global k base
                const int k0l = ks * 8;             // local k base in chunk
                // ---- A fragment (per-lane scalar loads + act + cvt) ----
                float av[4];
                if (full) {
                    av[0] = X[(size_t)ra * K + k0g + tig];
                    av[1] = X[(size_t)rb * K + k0g + tig];
                    av[2] = X[(size_t)ra * K + k0g + tig + 4];
                    av[3] = X[(size_t)rb * K + k0g + tig + 4];
                } else {
                    av[0] = (ra < N) ? X[(size_t)ra * K + k0g + tig] : 0.f;
                    av[1] = (rb < N) ? X[(size_t)rb * K + k0g + tig] : 0.f;
                    av[2] = (ra < N) ? X[(size_t)ra * K + k0g + tig + 4] : 0.f;
                    av[3] = (rb < N) ? X[(size_t)rb * K + k0g + tig + 4] : 0.f;
                }
                if (MODE) {
                    float a0 = sa[k0g + tig],     c0v = sc[k0g + tig];
                    float a1 = sa[k0g + tig + 4], c1v = sc[k0g + tig + 4];
                    av[0] = fmaxf(a0 * av[0] + c0v, 0.f);
                    av[1] = fmaxf(a0 * av[1] + c0v, 0.f);
                    av[2] = fmaxf(a1 * av[2] + c1v, 0.f);
                    av[3] = fmaxf(a1 * av[3] + c1v, 0.f);
                }
                uint32_t a[4];
                a[0] = f2tf32(av[0]); a[1] = f2tf32(av[1]);
                a[2] = f2tf32(av[2]); a[3] = f2tf32(av[3]);

                // ---- B fragments from SMEM + 12 MMAs ----
                const uint32_t* w0p = Ws + (k0l + tig) * WST + g;
                const uint32_t* w1p = Ws + (k0l + tig + 4) * WST + g;
#pragma unroll
                for (int nt = 0; nt < 12; nt++)
                    mma_tf32(c[nt], a, w0p[nt * 8], w1p[nt * 8]);
            }
        }
    }

    // ---- epilogue: scale by dinv[row], store float2 per (row, n-tile) ----
    if (r0 < N) {
        float da = (ra < N) ? g_dinv[ra] : 0.f;
        float db = (rb < N) ? g_dinv[rb] : 0.f;
#pragma unroll
        for (int nt = 0; nt < 12; nt++) {
            int col = nt * 8 + 2 * tig;
            if (ra < N)
                *(float2*)(g_hA + (size_t)ra * 96 + col) =
                    make_float2(c[nt][0] * da, c[nt][1] * da);
            if (rb < N)
                *(float2*)(g_hA + (size_t)rb * 96 + col) =
                    make_float2(c[nt][2] * db, c[nt][3] * db);
        }
    }
}

// ---------------- FFMA GEMM (layer 3, OUT=32): fp32 precision ----------------
__device__ __forceinline__ float f4c(const float4& v, int kk) {
    switch (kk) { case 0: return v.x; case 1: return v.y; case 2: return v.z; default: return v.w; }
}

template <int K, int OUT, int RY, int MODE>
__global__ __launch_bounds__((OUT / 8) * RY)
void gemm_kernel(const float* __restrict__ Xarg, const float* __restrict__ W,
                 const float* __restrict__ gamma, const float* __restrict__ beta, int N) {
    constexpr int CG = OUT / 8;
    constexpr int C4 = OUT / 4;
    constexpr int NT = CG * RY;
    constexpr int SAB = (MODE != 0) ? K : 1;

    __shared__ float4 Ws[K * C4];
    __shared__ float sa[SAB];
    __shared__ float sc[SAB];

    const int tid = threadIdx.y * CG + threadIdx.x;
    const float4* W4 = (const float4*)W;
    for (int i = tid; i < K * C4; i += NT) Ws[i] = W4[i];
    if (MODE) {
        const float* st = g_stats + (MODE - 1) * 192;
        for (int f = tid; f < K; f += NT) {
            float invN = 1.0f / (float)N;
            float mu = st[f] * invN;
            float var = st[96 + f] * invN - mu * mu;
            float a = gamma[f] * rsqrtf(var + 1e-5f);
            sa[f] = a;
            sc[f] = beta[f] - mu * a;
        }
    }
    __syncthreads();

    const float* X = MODE ? (const float*)g_agg : Xarg;
    const int c = threadIdx.x;
    const int r0 = (blockIdx.x * RY + threadIdx.y) * 8;
    if (r0 >= N) return;
    const bool full = (r0 + 7 < N);

    const float4* X4 = (const float4*)X;
    constexpr int ldx = K / 4;

    float4 acc[8][2];
#pragma unroll
    for (int r = 0; r < 8; r++) {
        acc[r][0] = make_float4(0.f, 0.f, 0.f, 0.f);
        acc[r][1] = make_float4(0.f, 0.f, 0.f, 0.f);
    }

    for (int k4 = 0; k4 < K / 4; k4++) {
        float4 xr[8];
        float4 ba, bc;
        if (MODE) { ba = ((const float4*)sa)[k4]; bc = ((const float4*)sc)[k4]; }
#pragma unroll
        for (int r = 0; r < 8; r++) {
            int row = r0 + r;
            float4 v = (full || row < N) ? X4[(size_t)row * ldx + k4]
                                         : make_float4(0.f, 0.f, 0.f, 0.f);
            if (MODE) {
                v.x = fmaxf(ba.x * v.x + bc.x, 0.f);
                v.y = fmaxf(ba.y * v.y + bc.y, 0.f);
                v.z = fmaxf(ba.z * v.z + bc.z, 0.f);
                v.w = fmaxf(ba.w * v.w + bc.w, 0.f);
            }
            xr[r] = v;
        }
#pragma unroll
        for (int kk = 0; kk < 4; kk++) {
            float4 w0 = Ws[(k4 * 4 + kk) * C4 + 2 * c];
            float4 w1 = Ws[(k4 * 4 + kk) * C4 + 2 * c + 1];
#pragma unroll
            for (int r = 0; r < 8; r++) {
                float xv = f4c(xr[r], kk);
                acc[r][0].x += xv * w0.x; acc[r][0].y += xv * w0.y;
                acc[r][0].z += xv * w0.z; acc[r][0].w += xv * w0.w;
                acc[r][1].x += xv * w1.x; acc[r][1].y += xv * w1.y;
                acc[r][1].z += xv * w1.z; acc[r][1].w += xv * w1.w;
            }
        }
    }

    float4* Y4 = (float4*)g_hA;
#pragma unroll
    for (int r = 0; r < 8; r++) {
        int row = r0 + r;
        if (full || row < N) {
            float dr = g_dinv[row];
            float4 a0 = acc[r][0], a1 = acc[r][1];
            a0.x *= dr; a0.y *= dr; a0.z *= dr; a0.w *= dr;
            a1.x *= dr; a1.y *= dr; a1.z *= dr; a1.w *= dr;
            Y4[(size_t)row * C4 + 2 * c]     = a0;
            Y4[(size_t)row * C4 + 2 * c + 1] = a1;
        }
    }
}

// ---------------- gather96: warp per node, CSR in-edges ----------------
__global__ __launch_bounds__(256)
void gather96_kernel(const float* __restrict__ bias, int layer, int N) {
    __shared__ float sred[192];
    const int tid = threadIdx.x;
    for (int i = tid; i < 192; i += 256) sred[i] = 0.f;
    __syncthreads();

    const int lane = tid & 31;
    const int w = tid >> 5;
    const int c0 = lane, c1 = lane + 32, c2 = lane + 64;
    const float b0 = bias[c0], b1 = bias[c1], b2 = bias[c2];
    const int nwarps = gridDim.x * 8;

    float s0 = 0.f, s1 = 0.f, s2 = 0.f;
    float q0 = 0.f, q1 = 0.f, q2 = 0.f;

    for (int d = blockIdx.x * 8 + w; d < N; d += nwarps) {
        const int beg = g_off[d];
        const int end = g_off[d + 1];
        float a0 = 0.f, a1 = 0.f, a2 = 0.f;
        int j = beg;
        for (; j + 3 < end; j += 4) {
            int sa = g_srcs[j], sb = g_srcs[j + 1], sc = g_srcs[j + 2], se = g_srcs[j + 3];
            const float* ha = g_hA + (size_t)sa * 96;
            const float* hb = g_hA + (size_t)sb * 96;
            const float* hc = g_hA + (size_t)sc * 96;
            const float* he = g_hA + (size_t)se * 96;
            float x0a = ha[c0], x1a = ha[c1], x2a = ha[c2];
            float x0b = hb[c0], x1b = hb[c1], x2b = hb[c2];
            float x0c = hc[c0], x1c = hc[c1], x2c = hc[c2];
            float x0e = he[c0], x1e = he[c1], x2e = he[c2];
            a0 += (x0a + x0b) + (x0c + x0e);
            a1 += (x1a + x1b) + (x1c + x1e);
            a2 += (x2a + x2b) + (x2c + x2e);
        }
        for (; j < end; j++) {
            int sa = g_srcs[j];
            const float* ha = g_hA + (size_t)sa * 96;
            a0 += ha[c0]; a1 += ha[c1]; a2 += ha[c2];
        }
        const float dd = g_dinv[d];
        const float* hd = g_hA + (size_t)d * 96;
        a0 += hd[c0]; a1 += hd[c1]; a2 += hd[c2];
        float v0 = dd * a0 + b0;
        float v1 = dd * a1 + b1;
        float v2 = dd * a2 + b2;
        float* od = g_agg + (size_t)d * 96;
        od[c0] = v0; od[c1] = v1; od[c2] = v2;
        s0 += v0; s1 += v1; s2 += v2;
        q0 += v0 * v0; q1 += v1 * v1; q2 += v2 * v2;
    }

    atomicAdd(&sred[c0], s0); atomicAdd(&sred[c1], s1); atomicAdd(&sred[c2], s2);
    atomicAdd(&sred[96 + c0], q0); atomicAdd(&sred[96 + c1], q1); atomicAdd(&sred[96 + c2], q2);
    __syncthreads();
    float* st = g_stats + layer * 192;
    for (int i = tid; i < 192; i += 256) atomicAdd(&st[i], sred[i]);
}

// ---------------- layer-3: gather(32) + log_softmax, warp per node ----------------
__global__ __launch_bounds__(256)
void gather32_softmax_kernel(const float* __restrict__ b3, float* __restrict__ out, int N) {
    int d = blockIdx.x * 8 + (threadIdx.x >> 5);
    int lane = threadIdx.x & 31;
    if (d >= N) return;
    const int beg = g_off[d];
    const int end = g_off[d + 1];
    float a = 0.f;
    int j = beg;
    for (; j + 3 < end; j += 4) {
        int sa = g_srcs[j], sb = g_srcs[j + 1], sc = g_srcs[j + 2], se = g_srcs[j + 3];
        float xa = g_hA[(size_t)sa * 32 + lane];
        float xb = g_hA[(size_t)sb * 32 + lane];
        float xc = g_hA[(size_t)sc * 32 + lane];
        float xe = g_hA[(size_t)se * 32 + lane];
        a += (xa + xb) + (xc + xe);
    }
    for (; j < end; j++) {
        int sa = g_srcs[j];
        a += g_hA[(size_t)sa * 32 + lane];
    }
    float dd = g_dinv[d];
    a += g_hA[(size_t)d * 32 + lane];
    float v = dd * a + b3[lane];
    float m = v;
#pragma unroll
    for (int o = 16; o > 0; o >>= 1) m = fmaxf(m, __shfl_xor_sync(0xFFFFFFFFu, m, o));
    float s = expf(v - m);
#pragma unroll
    for (int o = 16; o > 0; o >>= 1) s += __shfl_xor_sync(0xFFFFFFFFu, s, o);
    out[(size_t)d * 32 + lane] = v - m - logf(s);
}

// ---------------- host ----------------
extern "C" void kernel_launch(void* const* d_in, const int* in_sizes, int n_in,
                              void* d_out, int out_size) {
    const float* x  = (const float*)d_in[0];
    const int* ei   = (const int*)d_in[1];   // int32 in practice (JAX x64 disabled)
    const float* W1 = (const float*)d_in[2];
    const float* b1 = (const float*)d_in[3];
    const float* W2 = (const float*)d_in[4];
    const float* b2 = (const float*)d_in[5];
    const float* W3 = (const float*)d_in[6];
    const float* b3 = (const float*)d_in[7];
    const float* g1 = (const float*)d_in[8];
    const float* be1 = (const float*)d_in[9];
    const float* g2 = (const float*)d_in[10];
    const float* be2 = (const float*)d_in[11];
    float* out = (float*)d_out;

    int N = in_sizes[0] / 128;
    int E = in_sizes[1] / 2;
    const int* src = ei;
    const int* dst = ei + E;
    int nb = (N + SCAN_BLK - 1) / SCAN_BLK;
    int gb = (N + 127) / 128;

    // --- CSR build ---
    k_zero<<<(N + 1023) / 1024, 1024>>>(N, nb);
    k_hist<<<(E + 255) / 256, 256>>>(dst, E);
    k_scan<<<nb, SCAN_BLK>>>(N);
    gemm_tf32_kernel<128, 0><<<gb, 256>>>(x, W1, nullptr, nullptr, N);
    k_reorder<<<(E + 255) / 256, 256>>>(src, dst, E);

    // --- layer 1 ---
    gather96_kernel<<<592, 256>>>(b1, 0, N);

    // --- layer 2 (BN+ReLU fused into A load, tf32) ---
    gemm_tf32_kernel<96, 1><<<gb, 256>>>(nullptr, W2, g1, be1, N);
    gather96_kernel<<<592, 256>>>(b2, 1, N);

    // --- layer 3 (fp32 FFMA, BN+ReLU fused), then gather + log_softmax ---
    gemm_kernel<96, 32, 32, 2><<<(N + 255) / 256, dim3(4, 32)>>>(nullptr, W3, g2, be2, N);
    gather32_softmax_kernel<<<(N + 7) / 8, 256>>>(b3, out, N);
}